// round 11
// baseline (speedup 1.0000x reference)
#include <cuda_runtime.h>

// QuantumLayer via Pauli-transfer closed form — single fused kernel.
//
// o_j = sum over the 41 even-Y Pauli strings t in {I,X,Y}^4 of
//       W_j[t] * prod_w (1 | cos th_w | sin th_w).
// Each block computes the 164 weights W_j[t] (params-only) in a short
// prologue (redundantly per block — removes the separate setup kernel and
// its graph-node overhead), then processes 4 batch items per thread as two
// f32x2 lane-pairs. Weight pairs are packed as ulonglong2 so each term
// needs 2x LDS.128 (broadcast) instead of 4x LDS.64.

typedef unsigned long long ull;

__device__ __forceinline__ ull pk(float a, float b) {
    ull r; asm("mov.b64 %0, {%1, %2};" : "=l"(r) : "f"(a), "f"(b)); return r;
}
__device__ __forceinline__ void upk(ull v, float& a, float& b) {
    asm("mov.b64 {%0, %1}, %2;" : "=f"(a), "=f"(b) : "l"(v));
}
__device__ __forceinline__ ull f2mul(ull a, ull b) {
    ull r; asm("mul.rn.f32x2 %0, %1, %2;" : "=l"(r) : "l"(a), "l"(b)); return r;
}
__device__ __forceinline__ ull f2fma(ull a, ull b, ull c) {
    ull r; asm("fma.rn.f32x2 %0, %1, %2, %3;" : "=l"(r) : "l"(a), "l"(b), "l"(c)); return r;
}

#define F2_ONE 0x3F8000003F800000ULL   // (1.0f, 1.0f)

// The 41 even-Y Pauli strings, encoded t0*27+t1*9+t2*3+t3 (0=I,1=X,2=Y),
// ascending — identical to the main loop's idx order.
// Derivation: prefix q=(t0,t1,t2) with even #Y -> {3q, 3q+1}; odd #Y -> {3q+2}.
__device__ const unsigned char ENC41[41] = {
     0,  1,  3,  4,  8,  9, 10, 12, 13, 17, 20, 23, 24, 25, 27, 28, 30, 31,
    35, 36, 37, 39, 40, 44, 47, 50, 51, 52, 56, 59, 60, 61, 65, 68, 69, 70,
    72, 73, 75, 76, 80
};

#define CNOTF(c_, t_)                                                         \
    {                                                                         \
        const int mc = 8 >> (c_), mt = 8 >> (t_);                             \
        _Pragma("unroll")                                                     \
        for (int k = 0; k < 16; ++k)                                          \
            if ((k & mc) && !(k & mt)) {                                      \
                float tmp = st[k]; st[k] = st[k | mt]; st[k | mt] = tmp;      \
            }                                                                 \
    }

#define SINCOS2(dc, ds, xa, xb)                                               \
    { float sa_, ca_, sb_, cb_;                                               \
      __sincosf(xa, &sa_, &ca_); __sincosf(xb, &sb_, &cb_);                   \
      dc = pk(ca_, cb_); ds = pk(sa_, sb_); }

__global__ void __launch_bounds__(256)
quantum_layer_kernel(const float4* __restrict__ inp,
                     const float*  __restrict__ params,
                     float4* __restrict__ out, int nquad, int B)
{
    __shared__ float sU[16][17];          // U columns: sU[m][k] = (U e_k)[m]
    __shared__ float sWf[164];            // scalar weights W[j*41 + tIdx]
    __shared__ ulonglong2 sWA[41];        // packed {W0, W1} per term
    __shared__ ulonglong2 sWB[41];        // packed {W2, W3} per term

    const int tid = threadIdx.x;

    // ---- Prologue A: 16 threads simulate the 16 columns of U (params-only).
    if (tid < 16) {
        float pc[8], ps[8];
#pragma unroll
        for (int g = 0; g < 8; ++g) {
            float th = 0.5f * __ldg(&params[g]);
            ps[g] = sinf(th); pc[g] = cosf(th);
        }
        float st[16];
#pragma unroll
        for (int i = 0; i < 16; ++i) st[i] = 0.0f;
        st[tid] = 1.0f;
        CNOTF(0, 1); CNOTF(1, 2); CNOTF(2, 3);
#pragma unroll
        for (int layer = 0; layer < 2; ++layer) {
#pragma unroll
            for (int w = 0; w < 4; ++w) {
                const float c = pc[layer * 4 + w], s = ps[layer * 4 + w];
                const int m = 8 >> w;
#pragma unroll
                for (int k = 0; k < 16; ++k)
                    if (!(k & m)) {
                        const int k1 = k | m;
                        float a0 = st[k], a1 = st[k1];
                        st[k]  = c * a0 - s * a1;
                        st[k1] = s * a0 + c * a1;
                    }
            }
            CNOTF(0, 1); CNOTF(1, 2); CNOTF(2, 3); CNOTF(3, 0);
        }
#pragma unroll
        for (int m = 0; m < 16; ++m) sU[m][tid] = st[m];
    }
    __syncthreads();

    // ---- Prologue B: 164 threads each compute one weight W_j[tIdx].
    if (tid < 164) {
        const int j = tid / 41, tIdx = tid - 41 * j;
        const int enc = ENC41[tIdx];
        const int t0 = enc / 27, t1 = (enc / 9) % 3, t2 = (enc / 3) % 3, t3 = enc % 3;
        const int ny = (t0 == 2) + (t1 == 2) + (t2 == 2) + (t3 == 2);
        const int f  = (t0 ? 8 : 0) | (t1 ? 4 : 0) | (t2 ? 2 : 0) | (t3 ? 1 : 0);
        const float sign0 = (ny == 2) ? -1.0f : 1.0f;   // i^nY for even nY

        float part = 0.0f;
#pragma unroll
        for (int l = 0; l < 16; ++l) {
            const int lf = l ^ f;
            float vl = 1.0f;                            // prod over Y wires of (1-2*bit)
            if (t0 == 2 && (l & 8)) vl = -vl;
            if (t1 == 2 && (l & 4)) vl = -vl;
            if (t2 == 2 && (l & 2)) vl = -vl;
            if (t3 == 2 && (l & 1)) vl = -vl;
            float oacc = 0.0f;                          // O_j[lf, l]
#pragma unroll
            for (int m = 0; m < 16; ++m) {
                float z = ((m >> (3 - j)) & 1) ? -1.0f : 1.0f;
                oacc += z * sU[m][lf] * sU[m][l];
            }
            part += vl * oacc;
        }
        sWf[tid] = sign0 * part * (1.0f / 16.0f);
    }
    __syncthreads();

    // ---- Prologue C: pack weights into f32x2 pairs.
    if (tid < 41) {
        float w0 = sWf[tid],      w1 = sWf[41 + tid];
        float w2 = sWf[82 + tid], w3 = sWf[123 + tid];
        sWA[tid] = make_ulonglong2(pk(w0, w0), pk(w1, w1));
        sWB[tid] = make_ulonglong2(pk(w2, w2), pk(w3, w3));
    }
    __syncthreads();

    // ---- Main body: 4 batch items per thread (lane-pairs P and Q).
    const int t = blockIdx.x * blockDim.x + tid;
    if (t >= nquad) return;

    const int i0 = 4 * t;
    const bool hB = (i0 + 1) < B, hC = (i0 + 2) < B, hD = (i0 + 3) < B;
    float4 inA = inp[i0];
    float4 inB = hB ? inp[i0 + 1] : inA;
    float4 inC = hC ? inp[i0 + 2] : inA;
    float4 inD = hD ? inp[i0 + 3] : inA;

    ull CP[4], SP[4], CQ[4], SQ[4];
    SINCOS2(CP[0], SP[0], inA.x, inB.x); SINCOS2(CQ[0], SQ[0], inC.x, inD.x);
    SINCOS2(CP[1], SP[1], inA.y, inB.y); SINCOS2(CQ[1], SQ[1], inC.y, inD.y);
    SINCOS2(CP[2], SP[2], inA.z, inB.z); SINCOS2(CQ[2], SQ[2], inC.z, inD.z);
    SINCOS2(CP[3], SP[3], inA.w, inB.w); SINCOS2(CQ[3], SQ[3], inC.w, inD.w);

    // Monomials over wires 0,1 for each lane-pair.
    ull mP01[9], mQ01[9];
    mP01[0] = F2_ONE;               mQ01[0] = F2_ONE;
    mP01[1] = CP[1];                mQ01[1] = CQ[1];
    mP01[2] = SP[1];                mQ01[2] = SQ[1];
    mP01[3] = CP[0];                mQ01[3] = CQ[0];
    mP01[6] = SP[0];                mQ01[6] = SQ[0];
    mP01[4] = f2mul(CP[0], CP[1]);  mQ01[4] = f2mul(CQ[0], CQ[1]);
    mP01[5] = f2mul(CP[0], SP[1]);  mQ01[5] = f2mul(CQ[0], SQ[1]);
    mP01[7] = f2mul(SP[0], CP[1]);  mQ01[7] = f2mul(SQ[0], CQ[1]);
    mP01[8] = f2mul(SP[0], SP[1]);  mQ01[8] = f2mul(SQ[0], SQ[1]);

    ull oP0 = 0, oP1 = 0, oP2 = 0, oP3 = 0;
    ull oQ0 = 0, oQ1 = 0, oQ2 = 0, oQ3 = 0;
    int idx = 0;
#pragma unroll
    for (int t0 = 0; t0 < 3; ++t0)
#pragma unroll
    for (int t1 = 0; t1 < 3; ++t1) {
        const int p01 = t0 * 3 + t1;
#pragma unroll
        for (int t2 = 0; t2 < 3; ++t2) {
            ull preP, preQ;
            bool preOne = false;
            if (t2 == 0) {
                preP = mP01[p01]; preQ = mQ01[p01]; preOne = (p01 == 0);
            } else if (p01 == 0) {
                preP = (t2 == 1) ? CP[2] : SP[2];
                preQ = (t2 == 1) ? CQ[2] : SQ[2];
            } else {
                preP = f2mul(mP01[p01], (t2 == 1) ? CP[2] : SP[2]);
                preQ = f2mul(mQ01[p01], (t2 == 1) ? CQ[2] : SQ[2]);
            }
#pragma unroll
            for (int t3 = 0; t3 < 3; ++t3) {
                const int ny = (t0 == 2) + (t1 == 2) + (t2 == 2) + (t3 == 2);
                if (ny & 1) continue;   // odd-Y strings have zero weight
                ull mP, mQ;
                if (t3 == 0) {
                    mP = preP; mQ = preQ;
                } else if (preOne) {
                    mP = (t3 == 1) ? CP[3] : SP[3];
                    mQ = (t3 == 1) ? CQ[3] : SQ[3];
                } else {
                    mP = f2mul(preP, (t3 == 1) ? CP[3] : SP[3]);
                    mQ = f2mul(preQ, (t3 == 1) ? CQ[3] : SQ[3]);
                }
                // 2x LDS.128 per term, reused by both lane-pairs.
                ulonglong2 wA = sWA[idx];   // {W0, W1}
                ulonglong2 wB = sWB[idx];   // {W2, W3}
                oP0 = f2fma(mP, wA.x, oP0);  oQ0 = f2fma(mQ, wA.x, oQ0);
                oP1 = f2fma(mP, wA.y, oP1);  oQ1 = f2fma(mQ, wA.y, oQ1);
                oP2 = f2fma(mP, wB.x, oP2);  oQ2 = f2fma(mQ, wB.x, oQ2);
                oP3 = f2fma(mP, wB.y, oP3);  oQ3 = f2fma(mQ, wB.y, oQ3);
                ++idx;
            }
        }
    }

    float a0, b0, a1, b1, a2, b2, a3, b3;
    upk(oP0, a0, b0); upk(oP1, a1, b1); upk(oP2, a2, b2); upk(oP3, a3, b3);
    out[i0] = make_float4(a0, a1, a2, a3);
    if (hB) out[i0 + 1] = make_float4(b0, b1, b2, b3);
    upk(oQ0, a0, b0); upk(oQ1, a1, b1); upk(oQ2, a2, b2); upk(oQ3, a3, b3);
    if (hC) out[i0 + 2] = make_float4(a0, a1, a2, a3);
    if (hD) out[i0 + 3] = make_float4(b0, b1, b2, b3);
}

extern "C" void kernel_launch(void* const* d_in, const int* in_sizes, int n_in,
                              void* d_out, int out_size)
{
    const float* inputs = (const float*)d_in[0];   // (B, 4) float32
    const float* params = (const float*)d_in[1];   // (2, 4) float32
    float* outp = (float*)d_out;                   // (B, 4) float32

    int B = in_sizes[0] / 4;
    int nquad = (B + 3) / 4;
    int threads = 256;
    int blocks = (nquad + threads - 1) / threads;

    quantum_layer_kernel<<<blocks, threads>>>((const float4*)inputs, params,
                                              (float4*)outp, nquad, B);
}

// round 12
// speedup vs baseline: 1.1721x; 1.1721x over previous
#include <cuda_runtime.h>

// QuantumLayer via Pauli-transfer closed form — single fused kernel.
//
// o_j = sum over the 41 even-Y Pauli strings t in {I,X,Y}^4 of
//       W_j[t] * prod_w (1 | cos th_w | sin th_w).
//
// Prologue (per block, redundant): each of the 8 warps simulates the fixed
// real orthogonal operator U (params-only) with lane (l&15) holding column
// (l&15) IN REGISTERS, then computes its share of the 41 weight quadruples
// using warp shuffles only (prod[m] = st[m] * shfl_xor(st[m], f)) — zero
// shared-memory traffic, ~1.5k cycles (the R10 prologue's smem-based dot
// products cost ~10k cycles/block and regressed the kernel 17->33us).
//
// Main body: 4 batch items per thread as two f32x2 lane-pairs; weight pairs
// packed as ulonglong2 so each term needs 2x LDS.128 broadcast.

typedef unsigned long long ull;

__device__ __forceinline__ ull pk(float a, float b) {
    ull r; asm("mov.b64 %0, {%1, %2};" : "=l"(r) : "f"(a), "f"(b)); return r;
}
__device__ __forceinline__ void upk(ull v, float& a, float& b) {
    asm("mov.b64 {%0, %1}, %2;" : "=f"(a), "=f"(b) : "l"(v));
}
__device__ __forceinline__ ull f2mul(ull a, ull b) {
    ull r; asm("mul.rn.f32x2 %0, %1, %2;" : "=l"(r) : "l"(a), "l"(b)); return r;
}
__device__ __forceinline__ ull f2fma(ull a, ull b, ull c) {
    ull r; asm("fma.rn.f32x2 %0, %1, %2, %3;" : "=l"(r) : "l"(a), "l"(b), "l"(c)); return r;
}

#define F2_ONE 0x3F8000003F800000ULL   // (1.0f, 1.0f)

// The 41 even-Y Pauli strings, encoded t0*27+t1*9+t2*3+t3 (0=I,1=X,2=Y),
// ascending — identical to the main loop's idx order. (Validated in R10.)
__device__ const unsigned char ENC41[41] = {
     0,  1,  3,  4,  8,  9, 10, 12, 13, 17, 20, 23, 24, 25, 27, 28, 30, 31,
    35, 36, 37, 39, 40, 44, 47, 50, 51, 52, 56, 59, 60, 61, 65, 68, 69, 70,
    72, 73, 75, 76, 80
};

#define CNOTF(c_, t_)                                                         \
    {                                                                         \
        const int mc = 8 >> (c_), mt = 8 >> (t_);                             \
        _Pragma("unroll")                                                     \
        for (int k = 0; k < 16; ++k)                                          \
            if ((k & mc) && !(k & mt)) {                                      \
                float tmp = st[k]; st[k] = st[k | mt]; st[k | mt] = tmp;      \
            }                                                                 \
    }

#define SINCOS2(dc, ds, xa, xb)                                               \
    { float sa_, ca_, sb_, cb_;                                               \
      __sincosf(xa, &sa_, &ca_); __sincosf(xb, &sb_, &cb_);                   \
      dc = pk(ca_, cb_); ds = pk(sa_, sb_); }

__global__ void __launch_bounds__(256)
quantum_layer_kernel(const float4* __restrict__ inp,
                     const float*  __restrict__ params,
                     float4* __restrict__ out, int nquad, int B)
{
    __shared__ ulonglong2 sWA[41];   // packed {W0, W1} per term
    __shared__ ulonglong2 sWB[41];   // packed {W2, W3} per term

    const int tid  = threadIdx.x;
    const int wid  = tid >> 5;
    const int lane = tid & 31;

    // ================= Prologue: weights via register-resident U + shuffles.
    {
        // Each lane simulates U's column (lane & 15); upper half duplicates.
        float pc[8], ps[8];
#pragma unroll
        for (int g = 0; g < 8; ++g)
            __sincosf(0.5f * __ldg(&params[g]), &ps[g], &pc[g]);

        float st[16];
        const int col = lane & 15;
#pragma unroll
        for (int i = 0; i < 16; ++i) st[i] = 0.0f;
        st[col] = 1.0f;   // dynamic index into 16-array: small, but avoid —
        // rewrite as predicated fill to keep st[] in registers:
#pragma unroll
        for (int i = 0; i < 16; ++i) st[i] = (i == col) ? 1.0f : 0.0f;

        CNOTF(0, 1); CNOTF(1, 2); CNOTF(2, 3);
#pragma unroll
        for (int layer = 0; layer < 2; ++layer) {
#pragma unroll
            for (int w = 0; w < 4; ++w) {
                const float c = pc[layer * 4 + w], s = ps[layer * 4 + w];
                const int m = 8 >> w;
#pragma unroll
                for (int k = 0; k < 16; ++k)
                    if (!(k & m)) {
                        const int k1 = k | m;
                        float a0 = st[k], a1 = st[k1];
                        st[k]  = c * a0 - s * a1;
                        st[k1] = s * a0 + c * a1;
                    }
            }
            CNOTF(0, 1); CNOTF(1, 2); CNOTF(2, 3); CNOTF(3, 0);
        }

        // Warp wid handles tIdx = wid, wid+8, ... (<=6 strings per warp).
        for (int tIdx = wid; tIdx < 41; tIdx += 8) {
            const int enc = ENC41[tIdx];
            const int t0 = enc / 27, t1 = (enc / 9) % 3,
                      t2 = (enc / 3) % 3, t3 = enc % 3;
            const int f     = (t0 ? 8 : 0) | (t1 ? 4 : 0) | (t2 ? 2 : 0) | (t3 ? 1 : 0);
            const int ymask = ((t0 == 2) ? 8 : 0) | ((t1 == 2) ? 4 : 0) |
                              ((t2 == 2) ? 2 : 0) | ((t3 == 2) ? 1 : 0);
            const int ny = __popc(ymask);
            const float sign0 = (ny == 2) ? -1.0f : 1.0f;   // i^nY for even nY

            // prod[m] = U[m, l] * U[m, l^f]  (f < 16: shuffle stays in half)
            float prod[16];
#pragma unroll
            for (int m = 0; m < 16; ++m) {
                float o = __shfl_xor_sync(0xffffffffu, st[m], f);
                prod[m] = st[m] * o;
            }

            // Four signed sums over m: S_j = sum_m prod[m] * (1 - 2*bit_{3-j}(m))
            float u[8], v[8];
#pragma unroll
            for (int a = 0; a < 8; ++a) {
                u[a] = prod[2 * a] + prod[2 * a + 1];
                v[a] = prod[2 * a] - prod[2 * a + 1];
            }
            float S3 = ((v[0] + v[1]) + (v[2] + v[3])) + ((v[4] + v[5]) + (v[6] + v[7]));
            float a2[4], b2[4];
#pragma unroll
            for (int b = 0; b < 4; ++b) {
                a2[b] = u[2 * b] + u[2 * b + 1];
                b2[b] = u[2 * b] - u[2 * b + 1];
            }
            float S2 = (b2[0] + b2[1]) + (b2[2] + b2[3]);
            float A0 = a2[0] + a2[1], B0 = a2[0] - a2[1];
            float A1 = a2[2] + a2[3], B1 = a2[2] - a2[3];
            float S1 = B0 + B1;
            float S0 = A0 - A1;

            // v(l) = parity sign of (l & ymask); fold in sign0/16.
            const float vl = (__popc(col & ymask) & 1) ? -1.0f : 1.0f;
            const float scale = vl * sign0 * 0.0625f;
            float w0 = S0 * scale, w1 = S1 * scale;
            float w2 = S2 * scale, w3 = S3 * scale;

            // Reduce over the 16 columns (xor offsets stay within half-warp).
#pragma unroll
            for (int off = 1; off < 16; off <<= 1) {
                w0 += __shfl_xor_sync(0xffffffffu, w0, off);
                w1 += __shfl_xor_sync(0xffffffffu, w1, off);
                w2 += __shfl_xor_sync(0xffffffffu, w2, off);
                w3 += __shfl_xor_sync(0xffffffffu, w3, off);
            }
            if (lane == 0) {
                sWA[tIdx] = make_ulonglong2(pk(w0, w0), pk(w1, w1));
                sWB[tIdx] = make_ulonglong2(pk(w2, w2), pk(w3, w3));
            }
        }
    }
    __syncthreads();

    // ================= Main body: 4 batch items per thread (pairs P, Q).
    const int t = blockIdx.x * blockDim.x + tid;
    if (t >= nquad) return;

    const int i0 = 4 * t;
    const bool hB = (i0 + 1) < B, hC = (i0 + 2) < B, hD = (i0 + 3) < B;
    float4 inA = inp[i0];
    float4 inB = hB ? inp[i0 + 1] : inA;
    float4 inC = hC ? inp[i0 + 2] : inA;
    float4 inD = hD ? inp[i0 + 3] : inA;

    ull CP[4], SP[4], CQ[4], SQ[4];
    SINCOS2(CP[0], SP[0], inA.x, inB.x); SINCOS2(CQ[0], SQ[0], inC.x, inD.x);
    SINCOS2(CP[1], SP[1], inA.y, inB.y); SINCOS2(CQ[1], SQ[1], inC.y, inD.y);
    SINCOS2(CP[2], SP[2], inA.z, inB.z); SINCOS2(CQ[2], SQ[2], inC.z, inD.z);
    SINCOS2(CP[3], SP[3], inA.w, inB.w); SINCOS2(CQ[3], SQ[3], inC.w, inD.w);

    // Monomials over wires 0,1 for each lane-pair.
    ull mP01[9], mQ01[9];
    mP01[0] = F2_ONE;               mQ01[0] = F2_ONE;
    mP01[1] = CP[1];                mQ01[1] = CQ[1];
    mP01[2] = SP[1];                mQ01[2] = SQ[1];
    mP01[3] = CP[0];                mQ01[3] = CQ[0];
    mP01[6] = SP[0];                mQ01[6] = SQ[0];
    mP01[4] = f2mul(CP[0], CP[1]);  mQ01[4] = f2mul(CQ[0], CQ[1]);
    mP01[5] = f2mul(CP[0], SP[1]);  mQ01[5] = f2mul(CQ[0], SQ[1]);
    mP01[7] = f2mul(SP[0], CP[1]);  mQ01[7] = f2mul(SQ[0], CQ[1]);
    mP01[8] = f2mul(SP[0], SP[1]);  mQ01[8] = f2mul(SQ[0], SQ[1]);

    ull oP0 = 0, oP1 = 0, oP2 = 0, oP3 = 0;
    ull oQ0 = 0, oQ1 = 0, oQ2 = 0, oQ3 = 0;
    int idx = 0;
#pragma unroll
    for (int t0 = 0; t0 < 3; ++t0)
#pragma unroll
    for (int t1 = 0; t1 < 3; ++t1) {
        const int p01 = t0 * 3 + t1;
#pragma unroll
        for (int t2 = 0; t2 < 3; ++t2) {
            ull preP, preQ;
            bool preOne = false;
            if (t2 == 0) {
                preP = mP01[p01]; preQ = mQ01[p01]; preOne = (p01 == 0);
            } else if (p01 == 0) {
                preP = (t2 == 1) ? CP[2] : SP[2];
                preQ = (t2 == 1) ? CQ[2] : SQ[2];
            } else {
                preP = f2mul(mP01[p01], (t2 == 1) ? CP[2] : SP[2]);
                preQ = f2mul(mQ01[p01], (t2 == 1) ? CQ[2] : SQ[2]);
            }
#pragma unroll
            for (int t3 = 0; t3 < 3; ++t3) {
                const int ny = (t0 == 2) + (t1 == 2) + (t2 == 2) + (t3 == 2);
                if (ny & 1) continue;   // odd-Y strings have zero weight
                ull mP, mQ;
                if (t3 == 0) {
                    mP = preP; mQ = preQ;
                } else if (preOne) {
                    mP = (t3 == 1) ? CP[3] : SP[3];
                    mQ = (t3 == 1) ? CQ[3] : SQ[3];
                } else {
                    mP = f2mul(preP, (t3 == 1) ? CP[3] : SP[3]);
                    mQ = f2mul(preQ, (t3 == 1) ? CQ[3] : SQ[3]);
                }
                // 2x LDS.128 per term, reused by both lane-pairs.
                ulonglong2 wA = sWA[idx];   // {W0, W1}
                ulonglong2 wB = sWB[idx];   // {W2, W3}
                oP0 = f2fma(mP, wA.x, oP0);  oQ0 = f2fma(mQ, wA.x, oQ0);
                oP1 = f2fma(mP, wA.y, oP1);  oQ1 = f2fma(mQ, wA.y, oQ1);
                oP2 = f2fma(mP, wB.x, oP2);  oQ2 = f2fma(mQ, wB.x, oQ2);
                oP3 = f2fma(mP, wB.y, oP3);  oQ3 = f2fma(mQ, wB.y, oQ3);
                ++idx;
            }
        }
    }

    float a0, b0, a1, b1, a2, b2, a3, b3;
    upk(oP0, a0, b0); upk(oP1, a1, b1); upk(oP2, a2, b2); upk(oP3, a3, b3);
    out[i0] = make_float4(a0, a1, a2, a3);
    if (hB) out[i0 + 1] = make_float4(b0, b1, b2, b3);
    upk(oQ0, a0, b0); upk(oQ1, a1, b1); upk(oQ2, a2, b2); upk(oQ3, a3, b3);
    if (hC) out[i0 + 2] = make_float4(a0, a1, a2, a3);
    if (hD) out[i0 + 3] = make_float4(b0, b1, b2, b3);
}

extern "C" void kernel_launch(void* const* d_in, const int* in_sizes, int n_in,
                              void* d_out, int out_size)
{
    const float* inputs = (const float*)d_in[0];   // (B, 4) float32
    const float* params = (const float*)d_in[1];   // (2, 4) float32
    float* outp = (float*)d_out;                   // (B, 4) float32

    int B = in_sizes[0] / 4;
    int nquad = (B + 3) / 4;
    int threads = 256;
    int blocks = (nquad + threads - 1) / threads;

    quantum_layer_kernel<<<blocks, threads>>>((const float4*)inputs, params,
                                              (float4*)outp, nquad, B);
}